// round 16
// baseline (speedup 1.0000x reference)
#include <cuda_runtime.h>
#include <cuda_fp16.h>
#include <math.h>
#include <stdint.h>

// ---------------- problem constants ----------------
#define D_MODEL   2048
#define NUM_HEADS 16
#define HEAD_DIM  128
#define BATCH     2
#define SEQ       2048
#define MROWS     (BATCH * SEQ)        // 4096

#define NELEM_X   (MROWS * D_MODEL)          // 8388608
#define NELEM_W   (D_MODEL * D_MODEL)        // 4194304
#define NELEM_WKV (D_MODEL * HEAD_DIM)       // 262144
#define NELEM_KV  (MROWS * HEAD_DIM)         // 524288

// ---------------- scratch (__device__ statics; no cudaMalloc) ----------
__device__ __align__(16) __half g_xq[NELEM_X];        // query single fp16
__device__ __align__(16) __half g_xk[NELEM_X];        // key single fp16
__device__ __align__(16) __half g_xv[NELEM_X];        // value single fp16
__device__ __align__(16) __half g_wq[NELEM_W];        // [N,K] single fp16
__device__ __align__(16) __half g_wk[NELEM_WKV];
__device__ __align__(16) __half g_wv[NELEM_WKV];
__device__ __align__(16) __half g_wo[NELEM_W];
__device__ __align__(16) __half g_q[NELEM_X];         // pre-scaled Q single
__device__ __align__(16) __half g_k[NELEM_KV];        // K single [b*s, d]
__device__ __align__(16) __half g_vt[NELEM_KV];       // V^T single [b][d, s]
__device__ __align__(16) __half g_a[NELEM_X];         // attn out single

// ---------------- low-level helpers ----------
__device__ __forceinline__ uint32_t smem_to_u32(const void* p) {
    uint32_t a;
    asm("{ .reg .u64 t; cvta.to.shared.u64 t, %1; cvt.u32.u64 %0, t; }" : "=r"(a) : "l"(p));
    return a;
}
#define CP16(dst, src) \
    asm volatile("cp.async.cg.shared.global [%0], [%1], 16;" :: "r"(dst), "l"(src))
#define CP_COMMIT() asm volatile("cp.async.commit_group;" ::: "memory")
#define CP_WAIT(n)  asm volatile("cp.async.wait_group %0;" :: "n"(n) : "memory")

__device__ __forceinline__ void ldsm4(uint32_t* r, uint32_t addr) {
    asm volatile("ldmatrix.sync.aligned.m8n8.x4.shared.b16 {%0,%1,%2,%3}, [%4];"
        : "=r"(r[0]), "=r"(r[1]), "=r"(r[2]), "=r"(r[3]) : "r"(addr));
}
// fp16 inputs, fp32 accumulate
__device__ __forceinline__ void mma16816h(float* c, const uint32_t* a, const uint32_t* b) {
    asm volatile("mma.sync.aligned.m16n8k16.row.col.f32.f16.f16.f32 "
        "{%0,%1,%2,%3}, {%4,%5,%6,%7}, {%8,%9}, {%0,%1,%2,%3};"
        : "+f"(c[0]), "+f"(c[1]), "+f"(c[2]), "+f"(c[3])
        : "r"(a[0]), "r"(a[1]), "r"(a[2]), "r"(a[3]), "r"(b[0]), "r"(b[1]));
}

// swizzled smem offset for (row r, 16B-chunk c) within a 64B-wide tile block
__device__ __forceinline__ uint32_t sw_off(int r, int c) {
    return (uint32_t)(r * 64 + ((c ^ ((r >> 1) & 3)) << 4));
}

// =====================================================================
// Combined conversion kernel (ONE launch):
//   [0, 8192)       : convT Wq / Wo  (z = bid>>12, 64x64 blocks each)
//   [8192, 8704)    : convT Wk / Wv  (z = rel>>8,  4x64 blocks each)
//   [8704, 33280)   : input conv     (z = rel>>13: q / k / v, all single)
// =====================================================================
__device__ __forceinline__ void convT_body(
    const float* __restrict__ W, __half* __restrict__ Th, int Kd, int Nd,
    int bx, int by)
{
    __shared__ float t[32][33];
    const int n0 = bx * 32, k0 = by * 32;
    const int tx = threadIdx.x & 31, ty = threadIdx.x >> 5;
#pragma unroll
    for (int i = 0; i < 4; i++)
        t[ty + i * 8][tx] = W[(size_t)(k0 + ty + i * 8) * Nd + n0 + tx];
    __syncthreads();
#pragma unroll
    for (int i = 0; i < 4; i++) {
        float v = t[tx][ty + i * 8];
        Th[(size_t)(n0 + ty + i * 8) * Kd + k0 + tx] = __float2half(v);
    }
}

__global__ void __launch_bounds__(256)
conv_combined(const float* __restrict__ query, const float* __restrict__ key,
              const float* __restrict__ value,
              const float* __restrict__ Wq, const float* __restrict__ Wk,
              const float* __restrict__ Wv, const float* __restrict__ Wo,
              __half* __restrict__ xq, __half* __restrict__ xk,
              __half* __restrict__ xv,
              __half* __restrict__ wq, __half* __restrict__ wk,
              __half* __restrict__ wv, __half* __restrict__ wo)
{
    const int bid = blockIdx.x;
    if (bid < 8192) {                 // big weight transposes
        const int z = bid >> 12;
        const int r = bid & 4095;
        convT_body(z ? Wo : Wq, z ? wo : wq, D_MODEL, D_MODEL, r & 63, r >> 6);
        return;
    }
    if (bid < 8704) {                 // small weight transposes
        const int r = bid - 8192;
        const int z = r >> 8;
        const int rr = r & 255;
        convT_body(z ? Wv : Wk, z ? wv : wk, D_MODEL, HEAD_DIM, rr & 3, rr >> 2);
        return;
    }
    // input conversions (all single fp16)
    const int r = bid - 8704;
    const int z = r >> 13;            // 0: query, 1: key, 2: value
    const int i = (r & 8191) * 256 + threadIdx.x;
    const float* x = (z == 0) ? query : (z == 1) ? key : value;
    __half* o = (z == 0) ? xq : (z == 1) ? xk : xv;
    float4 val = ((const float4*)x)[i];
    ((__half2*)o)[i * 2]     = __floats2half2_rn(val.x, val.y);
    ((__half2*)o)[i * 2 + 1] = __floats2half2_rn(val.z, val.w);
}

// =====================================================================
// SINGLE-fp16 GEMM body: C = A[M,K] @ B[N,K]^T (+bias)(*scale)
// CTA 128x128, BK=32, 3-stage cp.async, 8 warps (64x32 warp tile).
// EPI: 0 = fp32+bias, 2 = fp16 single (+bias, *scale),
//      3 = fp16 single transposed V^T store (+bias).
// =====================================================================
#define SSTAGE_B   16384                      // A 8K | B 8K
#define SSM_BYTES  (3 * SSTAGE_B)             // 49152

template<int EPI>
__device__ __forceinline__ void gemm_single_body(
            const __half* __restrict__ A, const __half* __restrict__ B,
            const float* __restrict__ bias,
            float* __restrict__ Cf, __half* __restrict__ Ch,
            int K, int lda, int ldb, int ldc, float scale,
            int row0, int col0)
{
    extern __shared__ char smem[];
    const uint32_t sb = smem_to_u32(smem);
    const int tid = threadIdx.x, lane = tid & 31, wid = tid >> 5;
    const int wm = wid & 1, wn = wid >> 1;

    const char* pA = (const char*)(A + (size_t)row0 * lda);
    const char* pB = (const char*)(B + (size_t)col0 * ldb);
    const size_t lda2 = (size_t)lda * 2, ldb2 = (size_t)ldb * 2;

    const int r0c = tid >> 2,            c0c = tid & 3;
    const int r1c = (tid + 256) >> 2,    c1c = (tid + 256) & 3;
    const uint32_t so0 = sw_off(r0c, c0c), so1 = sw_off(r1c, c1c);

    float acc[4][4][4];
#pragma unroll
    for (int a = 0; a < 4; a++)
#pragma unroll
        for (int b = 0; b < 4; b++)
#pragma unroll
            for (int c = 0; c < 4; c++) acc[a][b][c] = 0.0f;

    const int niter = K >> 5;

#define LOAD_S(s, kof) do {                                                  \
        const uint32_t bA = sb + (s) * SSTAGE_B;                             \
        const size_t kb = (size_t)(kof) * 2;                                 \
        CP16(bA + so0,        pA + r0c * lda2 + kb + c0c * 16);              \
        CP16(bA + so1,        pA + r1c * lda2 + kb + c1c * 16);              \
        CP16(bA + 8192 + so0, pB + r0c * ldb2 + kb + c0c * 16);              \
        CP16(bA + 8192 + so1, pB + r1c * ldb2 + kb + c1c * 16);              \
    } while (0)

    LOAD_S(0, 0);  CP_COMMIT();
    LOAD_S(1, 32); CP_COMMIT();

    for (int i = 0; i < niter; i++) {
        if (i < niter - 1) { CP_WAIT(1); } else { CP_WAIT(0); }
        __syncthreads();
        if (i + 2 < niter) { LOAD_S((i + 2) % 3, (i + 2) * 32); CP_COMMIT(); }

        const uint32_t sA = sb + (i % 3) * SSTAGE_B;
        const uint32_t sB = sA + 8192;
#pragma unroll
        for (int h = 0; h < 2; h++) {
            uint32_t ah[4][4], bh[2][4];
            const int chk = 2 * h + (lane >> 4);
#pragma unroll
            for (int mt = 0; mt < 4; mt++) {
                const int r = wm * 64 + mt * 16 + (lane & 15);
                ldsm4(ah[mt], sA + sw_off(r, chk));
            }
#pragma unroll
            for (int np = 0; np < 2; np++) {
                const int r = wn * 32 + np * 16 + (lane & 15);
                ldsm4(bh[np], sB + sw_off(r, chk));
            }
#pragma unroll
            for (int mt = 0; mt < 4; mt++)
#pragma unroll
                for (int nt = 0; nt < 4; nt++) {
                    const int np = nt >> 1, sel = nt & 1;
                    uint32_t bf[2] = { bh[np][sel], bh[np][sel + 2] };
                    mma16816h(acc[mt][nt], ah[mt], bf);
                }
        }
    }
#undef LOAD_S

#pragma unroll
    for (int mt = 0; mt < 4; mt++) {
#pragma unroll
        for (int nt = 0; nt < 4; nt++) {
            const float* a = acc[mt][nt];
            const int gr = row0 + wm * 64 + mt * 16 + (lane >> 2);
            const int gc = col0 + wn * 32 + nt * 8 + (lane & 3) * 2;
            if (EPI == 0) {
                float b0 = bias[gc], b1 = bias[gc + 1];
                float2 v0 = { a[0] + b0, a[1] + b1 };
                float2 v1 = { a[2] + b0, a[3] + b1 };
                *(float2*)&Cf[(size_t)gr * ldc + gc]       = v0;
                *(float2*)&Cf[(size_t)(gr + 8) * ldc + gc] = v1;
            } else if (EPI == 2) {
                const float b0 = bias[gc], b1 = bias[gc + 1];
                size_t o = (size_t)gr * ldc + gc;
                *(__half2*)&Ch[o] = __halves2half2(__float2half((a[0] + b0) * scale),
                                                   __float2half((a[1] + b1) * scale));
                o = (size_t)(gr + 8) * ldc + gc;
                *(__half2*)&Ch[o] = __halves2half2(__float2half((a[2] + b0) * scale),
                                                   __float2half((a[3] + b1) * scale));
            } else {  // EPI == 3: V^T single store: out[b][dim][token]
#pragma unroll
                for (int q = 0; q < 4; q++) {
                    const int rr = gr + (q >> 1) * 8;
                    const int cc = gc + (q & 1);
                    const float t = a[q] + bias[cc];
                    const size_t o = (size_t)(rr >> 11) * ((size_t)HEAD_DIM * SEQ)
                                   + (size_t)cc * SEQ + (rr & (SEQ - 1));
                    Ch[o] = __float2half(t);
                }
            }
        }
    }
}

// =====================================================================
// Combined projections (ONE launch, 576 uniform single-A tiles):
//   [0, 32)    : K projection  (N=128 tile, col0=0)
//   [32, 64)   : V projection  (transposed store)
//   [64, 576)  : Q projection  (scaled)
// =====================================================================
__global__ void __launch_bounds__(256, 2)
proj_combined(const __half* __restrict__ xq, const __half* __restrict__ xk,
              const __half* __restrict__ xv,
              const __half* __restrict__ wq, const __half* __restrict__ wk,
              const __half* __restrict__ wv,
              const float* __restrict__ bq, const float* __restrict__ bk,
              const float* __restrict__ bv,
              __half* __restrict__ q, __half* __restrict__ k,
              __half* __restrict__ vt, float scale)
{
    const int bid = blockIdx.x;
    if (bid < 32) {
        gemm_single_body<2>(xk, wk, bk, nullptr, k,
                            D_MODEL, D_MODEL, D_MODEL, HEAD_DIM, 1.0f,
                            bid * 128, 0);
    } else if (bid < 64) {
        gemm_single_body<3>(xv, wv, bv, nullptr, vt,
                            D_MODEL, D_MODEL, D_MODEL, 0, 1.0f,
                            (bid - 32) * 128, 0);
    } else {
        const int r = bid - 64;
        gemm_single_body<2>(xq, wq, bq, nullptr, q,
                            D_MODEL, D_MODEL, D_MODEL, D_MODEL, scale,
                            (r >> 4) * 128, (r & 15) * 128);
    }
}

// O-projection (separate: depends on flash output)
__global__ void __launch_bounds__(256, 2)
o_proj(const __half* __restrict__ A, const __half* __restrict__ B,
       const float* __restrict__ bias, float* __restrict__ Cf)
{
    gemm_single_body<0>(A, B, bias, Cf, nullptr,
                        D_MODEL, D_MODEL, D_MODEL, D_MODEL, 1.0f,
                        blockIdx.y * 128, blockIdx.x * 128);
}

// =====================================================================
// Fused flash attention (pure single-fp16 tensor ops, online softmax).
// CTA: 128 q rows x full KV sweep. 8 warps x 16 rows. KT=64 per iter.
// smem: 2 stages x 32KB (K 16K | Vt 16K) + Q 32KB @65536 = 96KB.
// =====================================================================
#define FL_STAGE  32768
#define FL_Q      65536
#define FL_SMEM   98304

__global__ void __launch_bounds__(256)
flash_mma(const __half* __restrict__ Qg,
          const __half* __restrict__ Kg, const __half* __restrict__ Vtg,
          __half* __restrict__ O)
{
    extern __shared__ char smem[];
    const uint32_t sb = smem_to_u32(smem);
    const int tid = threadIdx.x, lane = tid & 31, w = tid >> 5;
    const int q0 = blockIdx.x * 128;
    const int hh = blockIdx.y;
    const int b  = blockIdx.z;

    const char* pQ = (const char*)(Qg + ((size_t)(b * SEQ) + q0) * D_MODEL + hh * HEAD_DIM);
    const char* pK = (const char*)(Kg + (size_t)b * SEQ * HEAD_DIM);
    const char* pV = (const char*)(Vtg + (size_t)b * HEAD_DIM * SEQ);

#define LOAD_KV(stg, kv0) do {                                               \
        const uint32_t bb = sb + (uint32_t)(stg) * FL_STAGE;                 \
        _Pragma("unroll")                                                    \
        for (int i2 = 0; i2 < 4; i2++) {                                     \
            const int idx = tid + i2 * 256;                                  \
            const int r = idx >> 4, c = idx & 15;                            \
            const uint32_t d = bb + ((c >> 2) << 12) + sw_off(r, c & 3);     \
            const size_t so = (size_t)((kv0) + r) * 256 + (c & 3) * 16 + (c >> 2) * 64; \
            CP16(d, pK + so);                                                \
        }                                                                    \
        _Pragma("unroll")                                                    \
        for (int i2 = 0; i2 < 4; i2++) {                                     \
            const int idx = tid + i2 * 256;                                  \
            const int r = idx >> 3, c = idx & 7;                             \
            const uint32_t d = bb + 16384 + ((c >> 2) << 13) + sw_off(r, c & 3); \
            const size_t so = (size_t)r * (SEQ * 2) + (size_t)(kv0) * 2 + (c & 3) * 16 + (c >> 2) * 64; \
            CP16(d, pV + so);                                                \
        }                                                                    \
    } while (0)

    // stage Q once (single fp16, 32KB)
#pragma unroll
    for (int i2 = 0; i2 < 8; i2++) {
        const int idx = tid + i2 * 256;
        const int r = idx >> 4, c = idx & 15;
        const uint32_t d = sb + FL_Q + ((c >> 2) << 13) + sw_off(r, c & 3);
        const size_t so = (size_t)r * (D_MODEL * 2) + (c & 3) * 16 + (c >> 2) * 64;
        CP16(d, pQ + so);
    }
    CP_COMMIT();
    LOAD_KV(0, 0);
    CP_COMMIT();

    CP_WAIT(1);
    __syncthreads();

    // Q fragments: 8 k-steps
    uint32_t qf[8][4];
#pragma unroll
    for (int ks = 0; ks < 8; ks++) {
        const int blk = ks >> 1;
        const int c   = (ks & 1) * 2 + (lane >> 4);
        const int r   = w * 16 + (lane & 15);
        ldsm4(qf[ks], sb + FL_Q + (blk << 13) + sw_off(r, c));
    }

    float oacc[16][4];
#pragma unroll
    for (int nt = 0; nt < 16; nt++)
#pragma unroll
        for (int q = 0; q < 4; q++) oacc[nt][q] = 0.0f;
    float m0 = -1e30f, m1 = -1e30f, l0 = 0.0f, l1 = 0.0f;

    for (int it = 0; it < SEQ / 64; it++) {
        CP_WAIT(0);
        __syncthreads();
        if (it + 1 < SEQ / 64) { LOAD_KV((it + 1) & 1, (it + 1) * 64); CP_COMMIT(); }

        const uint32_t kb = sb + (uint32_t)(it & 1) * FL_STAGE;
        const uint32_t vb = kb + 16384;

        // -------- scores: S[16q x 64kv] = Q K^T --------
        float sacc[8][4];
#pragma unroll
        for (int nt = 0; nt < 8; nt++)
#pragma unroll
            for (int q = 0; q < 4; q++) sacc[nt][q] = 0.0f;

#pragma unroll
        for (int ks = 0; ks < 8; ks++) {
            const int blk = ks >> 1;
            const int cc  = (ks & 1) * 2 + (lane >> 4);
#pragma unroll
            for (int g = 0; g < 4; g++) {
                uint32_t kh4[4];
                const int r = g * 16 + (lane & 15);
                ldsm4(kh4, kb + (blk << 12) + sw_off(r, cc));
#pragma unroll
                for (int sel = 0; sel < 2; sel++) {
                    uint32_t f[2] = { kh4[sel], kh4[sel + 2] };
                    mma16816h(sacc[g * 2 + sel], qf[ks], f);
                }
            }
        }

        // -------- online softmax --------
        float mx0 = sacc[0][0], mx1 = sacc[0][2];
#pragma unroll
        for (int nt = 0; nt < 8; nt++) {
            mx0 = fmaxf(mx0, fmaxf(sacc[nt][0], sacc[nt][1]));
            mx1 = fmaxf(mx1, fmaxf(sacc[nt][2], sacc[nt][3]));
        }
        mx0 = fmaxf(mx0, __shfl_xor_sync(0xffffffffu, mx0, 1));
        mx0 = fmaxf(mx0, __shfl_xor_sync(0xffffffffu, mx0, 2));
        mx1 = fmaxf(mx1, __shfl_xor_sync(0xffffffffu, mx1, 1));
        mx1 = fmaxf(mx1, __shfl_xor_sync(0xffffffffu, mx1, 2));
        const float mn0 = fmaxf(m0, mx0), mn1 = fmaxf(m1, mx1);
        const float cr0 = __expf(m0 - mn0), cr1 = __expf(m1 - mn1);
        m0 = mn0; m1 = mn1;

        float s0 = 0.0f, s1 = 0.0f;
        uint32_t pp[8][2];
#pragma unroll
        for (int nt = 0; nt < 8; nt++) {
            const float p0 = __expf(sacc[nt][0] - mn0);
            const float p1 = __expf(sacc[nt][1] - mn0);
            const float p2 = __expf(sacc[nt][2] - mn1);
            const float p3 = __expf(sacc[nt][3] - mn1);
            s0 += p0 + p1;
            s1 += p2 + p3;
            __half2 x0 = __floats2half2_rn(p0, p1);
            __half2 x1 = __floats2half2_rn(p2, p3);
            pp[nt][0] = *(uint32_t*)&x0;
            pp[nt][1] = *(uint32_t*)&x1;
        }
        s0 += __shfl_xor_sync(0xffffffffu, s0, 1);
        s0 += __shfl_xor_sync(0xffffffffu, s0, 2);
        s1 += __shfl_xor_sync(0xffffffffu, s1, 1);
        s1 += __shfl_xor_sync(0xffffffffu, s1, 2);
        l0 = l0 * cr0 + s0;
        l1 = l1 * cr1 + s1;

#pragma unroll
        for (int nt = 0; nt < 16; nt++) {
            oacc[nt][0] *= cr0; oacc[nt][1] *= cr0;
            oacc[nt][2] *= cr1; oacc[nt][3] *= cr1;
        }

        // -------- PV: out += P[16x64] V[64x128] --------
#pragma unroll
        for (int kk = 0; kk < 4; kk++) {
            uint32_t ap[4] = { pp[2 * kk][0], pp[2 * kk][1],
                               pp[2 * kk + 1][0], pp[2 * kk + 1][1] };
            const int blk = kk >> 1;
            const int cc  = (kk & 1) * 2 + (lane >> 4);
#pragma unroll
            for (int g = 0; g < 8; g++) {
                uint32_t vh4[4];
                const int r = g * 16 + (lane & 15);
                ldsm4(vh4, vb + (blk << 13) + sw_off(r, cc));
#pragma unroll
                for (int sel = 0; sel < 2; sel++) {
                    uint32_t f[2] = { vh4[sel], vh4[sel + 2] };
                    mma16816h(oacc[g * 2 + sel], ap, f);
                }
            }
        }
    }
#undef LOAD_KV

    // -------- epilogue: normalize + single-fp16 store --------
    const float i0 = 1.0f / l0, i1 = 1.0f / l1;
    const size_t ro0 = ((size_t)(b * SEQ) + q0 + w * 16 + (lane >> 2)) * D_MODEL
                     + (size_t)hh * HEAD_DIM;
    const size_t ro1 = ro0 + (size_t)8 * D_MODEL;
#pragma unroll
    for (int nt = 0; nt < 16; nt++) {
        const int col = nt * 8 + (lane & 3) * 2;
        *(__half2*)&O[ro0 + col] = __floats2half2_rn(oacc[nt][0] * i0, oacc[nt][1] * i0);
        *(__half2*)&O[ro1 + col] = __floats2half2_rn(oacc[nt][2] * i1, oacc[nt][3] * i1);
    }
}

// =====================================================================
// launch (4 kernels total)
// =====================================================================
extern "C" void kernel_launch(void* const* d_in, const int* in_sizes, int n_in,
                              void* d_out, int out_size)
{
    const float* query = (const float*)d_in[0];
    const float* key   = (const float*)d_in[1];
    const float* value = (const float*)d_in[2];
    const float* Wq    = (const float*)d_in[3];
    const float* bq    = (const float*)d_in[4];
    const float* Wk    = (const float*)d_in[5];
    const float* bk    = (const float*)d_in[6];
    const float* Wv    = (const float*)d_in[7];
    const float* bv    = (const float*)d_in[8];
    const float* Wo    = (const float*)d_in[9];
    const float* bo    = (const float*)d_in[10];
    float* out = (float*)d_out;

    __half *xq, *xk, *xv;
    __half *wq, *wk, *wv, *wo;
    __half *q, *k, *vt, *a;
    cudaGetSymbolAddress((void**)&xq, g_xq);
    cudaGetSymbolAddress((void**)&xk, g_xk);
    cudaGetSymbolAddress((void**)&xv, g_xv);
    cudaGetSymbolAddress((void**)&wq, g_wq);   cudaGetSymbolAddress((void**)&wk, g_wk);
    cudaGetSymbolAddress((void**)&wv, g_wv);   cudaGetSymbolAddress((void**)&wo, g_wo);
    cudaGetSymbolAddress((void**)&q,  g_q);
    cudaGetSymbolAddress((void**)&k,  g_k);    cudaGetSymbolAddress((void**)&vt, g_vt);
    cudaGetSymbolAddress((void**)&a,  g_a);

    cudaFuncSetAttribute(proj_combined, cudaFuncAttributeMaxDynamicSharedMemorySize, SSM_BYTES);
    cudaFuncSetAttribute(o_proj,        cudaFuncAttributeMaxDynamicSharedMemorySize, SSM_BYTES);
    cudaFuncSetAttribute(flash_mma,     cudaFuncAttributeMaxDynamicSharedMemorySize, FL_SMEM);

    const float attn_scale = 0.08838834764831845f;  // 1/sqrt(128)

    // 1) all conversions, one launch (inputs all single fp16 now)
    conv_combined<<<33280, 256>>>(query, key, value, Wq, Wk, Wv, Wo,
                                  xq, xk, xv, wq, wk, wv, wo);

    // 2) Q + K + V projections, one launch, 576 uniform tiles
    proj_combined<<<576, 256, SSM_BYTES>>>(
        xq, xk, xv, wq, wk, wv, bq, bk, bv, q, k, vt, attn_scale);

    // 3) fused flash attention
    flash_mma<<<dim3(SEQ / 128, NUM_HEADS, BATCH), 256, FL_SMEM>>>(
        q, k, vt, a);

    // 4) output projection -> d_out (fp32 + bias)
    o_proj<<<dim3(D_MODEL / 128, MROWS / 128), 256, SSM_BYTES>>>(a, wo, bo, out);
}

// round 17
// speedup vs baseline: 1.5185x; 1.5185x over previous
#include <cuda_runtime.h>
#include <cuda_fp16.h>
#include <math.h>
#include <stdint.h>

// ---------------- problem constants ----------------
#define D_MODEL   2048
#define NUM_HEADS 16
#define HEAD_DIM  128
#define BATCH     2
#define SEQ       2048
#define MROWS     (BATCH * SEQ)        // 4096

#define NELEM_X   (MROWS * D_MODEL)          // 8388608
#define NELEM_W   (D_MODEL * D_MODEL)        // 4194304
#define NELEM_WKV (D_MODEL * HEAD_DIM)       // 262144
#define NELEM_KV  (MROWS * HEAD_DIM)         // 524288

// ---------------- scratch (__device__ statics; no cudaMalloc) ----------
__device__ __align__(16) __half g_xq[NELEM_X];        // query single fp16
__device__ __align__(16) __half g_xk[NELEM_X];        // key single fp16
__device__ __align__(16) __half g_xv[NELEM_X];        // value single fp16
__device__ __align__(16) __half g_wq[NELEM_W];        // [N,K] single fp16
__device__ __align__(16) __half g_wk[NELEM_WKV];
__device__ __align__(16) __half g_wv[NELEM_WKV];
__device__ __align__(16) __half g_wo[NELEM_W];
__device__ __align__(16) __half g_q[NELEM_X];         // pre-scaled Q single
__device__ __align__(16) __half g_k[NELEM_KV];        // K single [b*s, d]
__device__ __align__(16) __half g_vt[NELEM_KV];       // V^T single [b][d, s]
__device__ __align__(16) __half g_a[NELEM_X];         // attn out single

// ---------------- low-level helpers ----------
__device__ __forceinline__ uint32_t smem_to_u32(const void* p) {
    uint32_t a;
    asm("{ .reg .u64 t; cvta.to.shared.u64 t, %1; cvt.u32.u64 %0, t; }" : "=r"(a) : "l"(p));
    return a;
}
#define CP16(dst, src) \
    asm volatile("cp.async.cg.shared.global [%0], [%1], 16;" :: "r"(dst), "l"(src))
#define CP_COMMIT() asm volatile("cp.async.commit_group;" ::: "memory")
#define CP_WAIT(n)  asm volatile("cp.async.wait_group %0;" :: "n"(n) : "memory")

__device__ __forceinline__ void ldsm4(uint32_t* r, uint32_t addr) {
    asm volatile("ldmatrix.sync.aligned.m8n8.x4.shared.b16 {%0,%1,%2,%3}, [%4];"
        : "=r"(r[0]), "=r"(r[1]), "=r"(r[2]), "=r"(r[3]) : "r"(addr));
}
// fp16 inputs, fp32 accumulate
__device__ __forceinline__ void mma16816h(float* c, const uint32_t* a, const uint32_t* b) {
    asm volatile("mma.sync.aligned.m16n8k16.row.col.f32.f16.f16.f32 "
        "{%0,%1,%2,%3}, {%4,%5,%6,%7}, {%8,%9}, {%0,%1,%2,%3};"
        : "+f"(c[0]), "+f"(c[1]), "+f"(c[2]), "+f"(c[3])
        : "r"(a[0]), "r"(a[1]), "r"(a[2]), "r"(a[3]), "r"(b[0]), "r"(b[1]));
}

// swizzled smem offset for (row r, 16B-chunk c) within a 64B-wide tile block
__device__ __forceinline__ uint32_t sw_off(int r, int c) {
    return (uint32_t)(r * 64 + ((c ^ ((r >> 1) & 3)) << 4));
}

// =====================================================================
// Combined conversion kernel (ONE launch):
//   [0, 8192)       : convT Wq / Wo  (z = bid>>12, 64x64 blocks each)
//   [8192, 8704)    : convT Wk / Wv  (z = rel>>8,  4x64 blocks each)
//   [8704, 33280)   : input conv     (z = rel>>13: q / k / v, all single)
// =====================================================================
__device__ __forceinline__ void convT_body(
    const float* __restrict__ W, __half* __restrict__ Th, int Kd, int Nd,
    int bx, int by)
{
    __shared__ float t[32][33];
    const int n0 = bx * 32, k0 = by * 32;
    const int tx = threadIdx.x & 31, ty = threadIdx.x >> 5;
#pragma unroll
    for (int i = 0; i < 4; i++)
        t[ty + i * 8][tx] = W[(size_t)(k0 + ty + i * 8) * Nd + n0 + tx];
    __syncthreads();
#pragma unroll
    for (int i = 0; i < 4; i++) {
        float v = t[tx][ty + i * 8];
        Th[(size_t)(n0 + ty + i * 8) * Kd + k0 + tx] = __float2half(v);
    }
}

__global__ void __launch_bounds__(256)
conv_combined(const float* __restrict__ query, const float* __restrict__ key,
              const float* __restrict__ value,
              const float* __restrict__ Wq, const float* __restrict__ Wk,
              const float* __restrict__ Wv, const float* __restrict__ Wo,
              __half* __restrict__ xq, __half* __restrict__ xk,
              __half* __restrict__ xv,
              __half* __restrict__ wq, __half* __restrict__ wk,
              __half* __restrict__ wv, __half* __restrict__ wo)
{
    const int bid = blockIdx.x;
    if (bid < 8192) {                 // big weight transposes
        const int z = bid >> 12;
        const int r = bid & 4095;
        convT_body(z ? Wo : Wq, z ? wo : wq, D_MODEL, D_MODEL, r & 63, r >> 6);
        return;
    }
    if (bid < 8704) {                 // small weight transposes
        const int r = bid - 8192;
        const int z = r >> 8;
        const int rr = r & 255;
        convT_body(z ? Wv : Wk, z ? wv : wk, D_MODEL, HEAD_DIM, rr & 3, rr >> 2);
        return;
    }
    // input conversions (all single fp16)
    const int r = bid - 8704;
    const int z = r >> 13;            // 0: query, 1: key, 2: value
    const int i = (r & 8191) * 256 + threadIdx.x;
    const float* x = (z == 0) ? query : (z == 1) ? key : value;
    __half* o = (z == 0) ? xq : (z == 1) ? xk : xv;
    float4 val = ((const float4*)x)[i];
    ((__half2*)o)[i * 2]     = __floats2half2_rn(val.x, val.y);
    ((__half2*)o)[i * 2 + 1] = __floats2half2_rn(val.z, val.w);
}

// =====================================================================
// SINGLE-fp16 GEMM body: C = A[M,K] @ B[N,K]^T (+bias)(*scale)
// CTA 128x128, BK=32, 3-stage cp.async, 8 warps (64x32 warp tile).
// EPI: 0 = fp32+bias, 2 = fp16 single (+bias, *scale),
//      3 = fp16 single transposed V^T store (+bias).
// =====================================================================
#define SSTAGE_B   16384                      // A 8K | B 8K
#define SSM_BYTES  (3 * SSTAGE_B)             // 49152

template<int EPI>
__device__ __forceinline__ void gemm_single_body(
            const __half* __restrict__ A, const __half* __restrict__ B,
            const float* __restrict__ bias,
            float* __restrict__ Cf, __half* __restrict__ Ch,
            int K, int lda, int ldb, int ldc, float scale,
            int row0, int col0)
{
    extern __shared__ char smem[];
    const uint32_t sb = smem_to_u32(smem);
    const int tid = threadIdx.x, lane = tid & 31, wid = tid >> 5;
    const int wm = wid & 1, wn = wid >> 1;

    const char* pA = (const char*)(A + (size_t)row0 * lda);
    const char* pB = (const char*)(B + (size_t)col0 * ldb);
    const size_t lda2 = (size_t)lda * 2, ldb2 = (size_t)ldb * 2;

    const int r0c = tid >> 2,            c0c = tid & 3;
    const int r1c = (tid + 256) >> 2,    c1c = (tid + 256) & 3;
    const uint32_t so0 = sw_off(r0c, c0c), so1 = sw_off(r1c, c1c);

    float acc[4][4][4];
#pragma unroll
    for (int a = 0; a < 4; a++)
#pragma unroll
        for (int b = 0; b < 4; b++)
#pragma unroll
            for (int c = 0; c < 4; c++) acc[a][b][c] = 0.0f;

    const int niter = K >> 5;

#define LOAD_S(s, kof) do {                                                  \
        const uint32_t bA = sb + (s) * SSTAGE_B;                             \
        const size_t kb = (size_t)(kof) * 2;                                 \
        CP16(bA + so0,        pA + r0c * lda2 + kb + c0c * 16);              \
        CP16(bA + so1,        pA + r1c * lda2 + kb + c1c * 16);              \
        CP16(bA + 8192 + so0, pB + r0c * ldb2 + kb + c0c * 16);              \
        CP16(bA + 8192 + so1, pB + r1c * ldb2 + kb + c1c * 16);              \
    } while (0)

    LOAD_S(0, 0);  CP_COMMIT();
    LOAD_S(1, 32); CP_COMMIT();

    for (int i = 0; i < niter; i++) {
        if (i < niter - 1) { CP_WAIT(1); } else { CP_WAIT(0); }
        __syncthreads();
        if (i + 2 < niter) { LOAD_S((i + 2) % 3, (i + 2) * 32); CP_COMMIT(); }

        const uint32_t sA = sb + (i % 3) * SSTAGE_B;
        const uint32_t sB = sA + 8192;
#pragma unroll
        for (int h = 0; h < 2; h++) {
            uint32_t ah[4][4], bh[2][4];
            const int chk = 2 * h + (lane >> 4);
#pragma unroll
            for (int mt = 0; mt < 4; mt++) {
                const int r = wm * 64 + mt * 16 + (lane & 15);
                ldsm4(ah[mt], sA + sw_off(r, chk));
            }
#pragma unroll
            for (int np = 0; np < 2; np++) {
                const int r = wn * 32 + np * 16 + (lane & 15);
                ldsm4(bh[np], sB + sw_off(r, chk));
            }
#pragma unroll
            for (int mt = 0; mt < 4; mt++)
#pragma unroll
                for (int nt = 0; nt < 4; nt++) {
                    const int np = nt >> 1, sel = nt & 1;
                    uint32_t bf[2] = { bh[np][sel], bh[np][sel + 2] };
                    mma16816h(acc[mt][nt], ah[mt], bf);
                }
        }
    }
#undef LOAD_S

#pragma unroll
    for (int mt = 0; mt < 4; mt++) {
#pragma unroll
        for (int nt = 0; nt < 4; nt++) {
            const float* a = acc[mt][nt];
            const int gr = row0 + wm * 64 + mt * 16 + (lane >> 2);
            const int gc = col0 + wn * 32 + nt * 8 + (lane & 3) * 2;
            if (EPI == 0) {
                float b0 = bias[gc], b1 = bias[gc + 1];
                float2 v0 = { a[0] + b0, a[1] + b1 };
                float2 v1 = { a[2] + b0, a[3] + b1 };
                *(float2*)&Cf[(size_t)gr * ldc + gc]       = v0;
                *(float2*)&Cf[(size_t)(gr + 8) * ldc + gc] = v1;
            } else if (EPI == 2) {
                const float b0 = bias[gc], b1 = bias[gc + 1];
                size_t o = (size_t)gr * ldc + gc;
                *(__half2*)&Ch[o] = __halves2half2(__float2half((a[0] + b0) * scale),
                                                   __float2half((a[1] + b1) * scale));
                o = (size_t)(gr + 8) * ldc + gc;
                *(__half2*)&Ch[o] = __halves2half2(__float2half((a[2] + b0) * scale),
                                                   __float2half((a[3] + b1) * scale));
            } else {  // EPI == 3: V^T single store: out[b][dim][token]
#pragma unroll
                for (int q = 0; q < 4; q++) {
                    const int rr = gr + (q >> 1) * 8;
                    const int cc = gc + (q & 1);
                    const float t = a[q] + bias[cc];
                    const size_t o = (size_t)(rr >> 11) * ((size_t)HEAD_DIM * SEQ)
                                   + (size_t)cc * SEQ + (rr & (SEQ - 1));
                    Ch[o] = __float2half(t);
                }
            }
        }
    }
}

// =====================================================================
// Combined projections (ONE launch, 576 uniform single-A tiles):
//   [0, 32)    : K projection  (N=128 tile, col0=0)
//   [32, 64)   : V projection  (transposed store)
//   [64, 576)  : Q projection  (scaled)
// =====================================================================
__global__ void __launch_bounds__(256, 2)
proj_combined(const __half* __restrict__ xq, const __half* __restrict__ xk,
              const __half* __restrict__ xv,
              const __half* __restrict__ wq, const __half* __restrict__ wk,
              const __half* __restrict__ wv,
              const float* __restrict__ bq, const float* __restrict__ bk,
              const float* __restrict__ bv,
              __half* __restrict__ q, __half* __restrict__ k,
              __half* __restrict__ vt, float scale)
{
    const int bid = blockIdx.x;
    if (bid < 32) {
        gemm_single_body<2>(xk, wk, bk, nullptr, k,
                            D_MODEL, D_MODEL, D_MODEL, HEAD_DIM, 1.0f,
                            bid * 128, 0);
    } else if (bid < 64) {
        gemm_single_body<3>(xv, wv, bv, nullptr, vt,
                            D_MODEL, D_MODEL, D_MODEL, 0, 1.0f,
                            (bid - 32) * 128, 0);
    } else {
        const int r = bid - 64;
        gemm_single_body<2>(xq, wq, bq, nullptr, q,
                            D_MODEL, D_MODEL, D_MODEL, D_MODEL, scale,
                            (r >> 4) * 128, (r & 15) * 128);
    }
}

// O-projection (separate: depends on flash output)
__global__ void __launch_bounds__(256, 2)
o_proj(const __half* __restrict__ A, const __half* __restrict__ B,
       const float* __restrict__ bias, float* __restrict__ Cf)
{
    gemm_single_body<0>(A, B, bias, Cf, nullptr,
                        D_MODEL, D_MODEL, D_MODEL, D_MODEL, 1.0f,
                        blockIdx.y * 128, blockIdx.x * 128);
}

// =====================================================================
// Fused flash attention (pure single-fp16 tensor ops, online softmax).
// CTA: 128 q rows x full KV sweep. 8 warps x 16 rows. KT=64 per iter.
// smem: 2 stages x 32KB (K 16K | Vt 16K) + Q 32KB @65536 = 96KB.
// =====================================================================
#define FL_STAGE  32768
#define FL_Q      65536
#define FL_SMEM   98304

__global__ void __launch_bounds__(256)
flash_mma(const __half* __restrict__ Qg,
          const __half* __restrict__ Kg, const __half* __restrict__ Vtg,
          __half* __restrict__ O)
{
    extern __shared__ char smem[];
    const uint32_t sb = smem_to_u32(smem);
    const int tid = threadIdx.x, lane = tid & 31, w = tid >> 5;
    const int q0 = blockIdx.x * 128;
    const int hh = blockIdx.y;
    const int b  = blockIdx.z;

    const char* pQ = (const char*)(Qg + ((size_t)(b * SEQ) + q0) * D_MODEL + hh * HEAD_DIM);
    const char* pK = (const char*)(Kg + (size_t)b * SEQ * HEAD_DIM);
    const char* pV = (const char*)(Vtg + (size_t)b * HEAD_DIM * SEQ);

#define LOAD_KV(stg, kv0) do {                                               \
        const uint32_t bb = sb + (uint32_t)(stg) * FL_STAGE;                 \
        _Pragma("unroll")                                                    \
        for (int i2 = 0; i2 < 4; i2++) {                                     \
            const int idx = tid + i2 * 256;                                  \
            const int r = idx >> 4, c = idx & 15;                            \
            const uint32_t d = bb + ((c >> 2) << 12) + sw_off(r, c & 3);     \
            const size_t so = (size_t)((kv0) + r) * 256 + (c & 3) * 16 + (c >> 2) * 64; \
            CP16(d, pK + so);                                                \
        }                                                                    \
        _Pragma("unroll")                                                    \
        for (int i2 = 0; i2 < 4; i2++) {                                     \
            const int idx = tid + i2 * 256;                                  \
            const int r = idx >> 3, c = idx & 7;                             \
            const uint32_t d = bb + 16384 + ((c >> 2) << 13) + sw_off(r, c & 3); \
            const size_t so = (size_t)r * (SEQ * 2) + (size_t)(kv0) * 2 + (c & 3) * 16 + (c >> 2) * 64; \
            CP16(d, pV + so);                                                \
        }                                                                    \
    } while (0)

    // stage Q once (single fp16, 32KB)
#pragma unroll
    for (int i2 = 0; i2 < 8; i2++) {
        const int idx = tid + i2 * 256;
        const int r = idx >> 4, c = idx & 15;
        const uint32_t d = sb + FL_Q + ((c >> 2) << 13) + sw_off(r, c & 3);
        const size_t so = (size_t)r * (D_MODEL * 2) + (c & 3) * 16 + (c >> 2) * 64;
        CP16(d, pQ + so);
    }
    CP_COMMIT();
    LOAD_KV(0, 0);
    CP_COMMIT();

    CP_WAIT(1);
    __syncthreads();

    // Q fragments: 8 k-steps
    uint32_t qf[8][4];
#pragma unroll
    for (int ks = 0; ks < 8; ks++) {
        const int blk = ks >> 1;
        const int c   = (ks & 1) * 2 + (lane >> 4);
        const int r   = w * 16 + (lane & 15);
        ldsm4(qf[ks], sb + FL_Q + (blk << 13) + sw_off(r, c));
    }

    float oacc[16][4];
#pragma unroll
    for (int nt = 0; nt < 16; nt++)
#pragma unroll
        for (int q = 0; q < 4; q++) oacc[nt][q] = 0.0f;
    float m0 = -1e30f, m1 = -1e30f, l0 = 0.0f, l1 = 0.0f;

    for (int it = 0; it < SEQ / 64; it++) {
        CP_WAIT(0);
        __syncthreads();
        if (it + 1 < SEQ / 64) { LOAD_KV((it + 1) & 1, (it + 1) * 64); CP_COMMIT(); }

        const uint32_t kb = sb + (uint32_t)(it & 1) * FL_STAGE;
        const uint32_t vb = kb + 16384;

        // -------- scores: S[16q x 64kv] = Q K^T --------
        float sacc[8][4];
#pragma unroll
        for (int nt = 0; nt < 8; nt++)
#pragma unroll
            for (int q = 0; q < 4; q++) sacc[nt][q] = 0.0f;

#pragma unroll
        for (int ks = 0; ks < 8; ks++) {
            const int blk = ks >> 1;
            const int cc  = (ks & 1) * 2 + (lane >> 4);
#pragma unroll
            for (int g = 0; g < 4; g++) {
                uint32_t kh4[4];
                const int r = g * 16 + (lane & 15);
                ldsm4(kh4, kb + (blk << 12) + sw_off(r, cc));
#pragma unroll
                for (int sel = 0; sel < 2; sel++) {
                    uint32_t f[2] = { kh4[sel], kh4[sel + 2] };
                    mma16816h(sacc[g * 2 + sel], qf[ks], f);
                }
            }
        }

        // -------- online softmax --------
        float mx0 = sacc[0][0], mx1 = sacc[0][2];
#pragma unroll
        for (int nt = 0; nt < 8; nt++) {
            mx0 = fmaxf(mx0, fmaxf(sacc[nt][0], sacc[nt][1]));
            mx1 = fmaxf(mx1, fmaxf(sacc[nt][2], sacc[nt][3]));
        }
        mx0 = fmaxf(mx0, __shfl_xor_sync(0xffffffffu, mx0, 1));
        mx0 = fmaxf(mx0, __shfl_xor_sync(0xffffffffu, mx0, 2));
        mx1 = fmaxf(mx1, __shfl_xor_sync(0xffffffffu, mx1, 1));
        mx1 = fmaxf(mx1, __shfl_xor_sync(0xffffffffu, mx1, 2));
        const float mn0 = fmaxf(m0, mx0), mn1 = fmaxf(m1, mx1);
        const float cr0 = __expf(m0 - mn0), cr1 = __expf(m1 - mn1);
        m0 = mn0; m1 = mn1;

        float s0 = 0.0f, s1 = 0.0f;
        uint32_t pp[8][2];
#pragma unroll
        for (int nt = 0; nt < 8; nt++) {
            const float p0 = __expf(sacc[nt][0] - mn0);
            const float p1 = __expf(sacc[nt][1] - mn0);
            const float p2 = __expf(sacc[nt][2] - mn1);
            const float p3 = __expf(sacc[nt][3] - mn1);
            s0 += p0 + p1;
            s1 += p2 + p3;
            __half2 x0 = __floats2half2_rn(p0, p1);
            __half2 x1 = __floats2half2_rn(p2, p3);
            pp[nt][0] = *(uint32_t*)&x0;
            pp[nt][1] = *(uint32_t*)&x1;
        }
        s0 += __shfl_xor_sync(0xffffffffu, s0, 1);
        s0 += __shfl_xor_sync(0xffffffffu, s0, 2);
        s1 += __shfl_xor_sync(0xffffffffu, s1, 1);
        s1 += __shfl_xor_sync(0xffffffffu, s1, 2);
        l0 = l0 * cr0 + s0;
        l1 = l1 * cr1 + s1;

#pragma unroll
        for (int nt = 0; nt < 16; nt++) {
            oacc[nt][0] *= cr0; oacc[nt][1] *= cr0;
            oacc[nt][2] *= cr1; oacc[nt][3] *= cr1;
        }

        // -------- PV: out += P[16x64] V[64x128] --------
#pragma unroll
        for (int kk = 0; kk < 4; kk++) {
            uint32_t ap[4] = { pp[2 * kk][0], pp[2 * kk][1],
                               pp[2 * kk + 1][0], pp[2 * kk + 1][1] };
            const int blk = kk >> 1;
            const int cc  = (kk & 1) * 2 + (lane >> 4);
#pragma unroll
            for (int g = 0; g < 8; g++) {
                uint32_t vh4[4];
                const int r = g * 16 + (lane & 15);
                ldsm4(vh4, vb + (blk << 13) + sw_off(r, cc));
#pragma unroll
                for (int sel = 0; sel < 2; sel++) {
                    uint32_t f[2] = { vh4[sel], vh4[sel + 2] };
                    mma16816h(oacc[g * 2 + sel], ap, f);
                }
            }
        }
    }
#undef LOAD_KV

    // -------- epilogue: normalize + single-fp16 store --------
    const float i0 = 1.0f / l0, i1 = 1.0f / l1;
    const size_t ro0 = ((size_t)(b * SEQ) + q0 + w * 16 + (lane >> 2)) * D_MODEL
                     + (size_t)hh * HEAD_DIM;
    const size_t ro1 = ro0 + (size_t)8 * D_MODEL;
#pragma unroll
    for (int nt = 0; nt < 16; nt++) {
        const int col = nt * 8 + (lane & 3) * 2;
        *(__half2*)&O[ro0 + col] = __floats2half2_rn(oacc[nt][0] * i0, oacc[nt][1] * i0);
        *(__half2*)&O[ro1 + col] = __floats2half2_rn(oacc[nt][2] * i1, oacc[nt][3] * i1);
    }
}

// =====================================================================
// launch (4 kernels total)
// =====================================================================
extern "C" void kernel_launch(void* const* d_in, const int* in_sizes, int n_in,
                              void* d_out, int out_size)
{
    const float* query = (const float*)d_in[0];
    const float* key   = (const float*)d_in[1];
    const float* value = (const float*)d_in[2];
    const float* Wq    = (const float*)d_in[3];
    const float* bq    = (const float*)d_in[4];
    const float* Wk    = (const float*)d_in[5];
    const float* bk    = (const float*)d_in[6];
    const float* Wv    = (const float*)d_in[7];
    const float* bv    = (const float*)d_in[8];
    const float* Wo    = (const float*)d_in[9];
    const float* bo    = (const float*)d_in[10];
    float* out = (float*)d_out;

    __half *xq, *xk, *xv;
    __half *wq, *wk, *wv, *wo;
    __half *q, *k, *vt, *a;
    cudaGetSymbolAddress((void**)&xq, g_xq);
    cudaGetSymbolAddress((void**)&xk, g_xk);
    cudaGetSymbolAddress((void**)&xv, g_xv);
    cudaGetSymbolAddress((void**)&wq, g_wq);   cudaGetSymbolAddress((void**)&wk, g_wk);
    cudaGetSymbolAddress((void**)&wv, g_wv);   cudaGetSymbolAddress((void**)&wo, g_wo);
    cudaGetSymbolAddress((void**)&q,  g_q);
    cudaGetSymbolAddress((void**)&k,  g_k);    cudaGetSymbolAddress((void**)&vt, g_vt);
    cudaGetSymbolAddress((void**)&a,  g_a);

    cudaFuncSetAttribute(proj_combined, cudaFuncAttributeMaxDynamicSharedMemorySize, SSM_BYTES);
    cudaFuncSetAttribute(o_proj,        cudaFuncAttributeMaxDynamicSharedMemorySize, SSM_BYTES);
    cudaFuncSetAttribute(flash_mma,     cudaFuncAttributeMaxDynamicSharedMemorySize, FL_SMEM);

    const float attn_scale = 0.08838834764831845f;  // 1/sqrt(128)

    // 1) all conversions, one launch (inputs all single fp16 now)
    conv_combined<<<33280, 256>>>(query, key, value, Wq, Wk, Wv, Wo,
                                  xq, xk, xv, wq, wk, wv, wo);

    // 2) Q + K + V projections, one launch, 576 uniform tiles
    proj_combined<<<576, 256, SSM_BYTES>>>(
        xq, xk, xv, wq, wk, wv, bq, bk, bv, q, k, vt, attn_scale);

    // 3) fused flash attention
    flash_mma<<<dim3(SEQ / 128, NUM_HEADS, BATCH), 256, FL_SMEM>>>(
        q, k, vt, a);

    // 4) output projection -> d_out (fp32 + bias)
    o_proj<<<dim3(D_MODEL / 128, MROWS / 128), 256, SSM_BYTES>>>(a, wo, bo, out);
}